// round 7
// baseline (speedup 1.0000x reference)
#include <cuda_runtime.h>

// Fixed problem shape
#define CC      20
#define HW_     (512 * 512)           // 262144 = 2^18
#define BATCH_  8
#define NPIX    (BATCH_ * HW_)        // 2,097,152 pixels
#define THREADS 256
#define PPT     4
#define GRID    (NPIX / (THREADS * PPT))   // 2048 blocks

// Per-block deterministic partials (overwritten every launch; no init needed)
__device__ float        g_part0[GRID];   // sum log(g10)
__device__ float        g_part1[GRID];   // sum log(g5)
__device__ float        g_part2[GRID];   // sum v_t  (= log exp(v_t))
__device__ float        g_part3[GRID];   // sum log(total)
__device__ unsigned int g_count = 0;     // last-block-done counter (self-resetting)

__device__ __forceinline__ void block_reduce4(float& a0, float& a1, float& a2, float& a3,
                                              float* sm0, float* sm1, float* sm2, float* sm3)
{
#pragma unroll
    for (int off = 16; off > 0; off >>= 1) {
        a0 += __shfl_down_sync(0xFFFFFFFFu, a0, off);
        a1 += __shfl_down_sync(0xFFFFFFFFu, a1, off);
        a2 += __shfl_down_sync(0xFFFFFFFFu, a2, off);
        a3 += __shfl_down_sync(0xFFFFFFFFu, a3, off);
    }
    const int lane = threadIdx.x & 31;
    const int wid  = threadIdx.x >> 5;
    if (lane == 0) { sm0[wid] = a0; sm1[wid] = a1; sm2[wid] = a2; sm3[wid] = a3; }
    __syncthreads();
    if (wid == 0) {
        const int nw = THREADS / 32;
        a0 = (lane < nw) ? sm0[lane] : 0.f;
        a1 = (lane < nw) ? sm1[lane] : 0.f;
        a2 = (lane < nw) ? sm2[lane] : 0.f;
        a3 = (lane < nw) ? sm3[lane] : 0.f;
#pragma unroll
        for (int off = 4; off > 0; off >>= 1) {
            a0 += __shfl_down_sync(0xFFFFFFFFu, a0, off);
            a1 += __shfl_down_sync(0xFFFFFFFFu, a1, off);
            a2 += __shfl_down_sync(0xFFFFFFFFu, a2, off);
            a3 += __shfl_down_sync(0xFFFFFFFFu, a3, off);
        }
    }
}

__global__ __launch_bounds__(THREADS, 3)
void tce_kernel(const float* __restrict__ logits,
                const int*   __restrict__ targets,
                float* __restrict__ out, int out_size)
{
    const int q = (blockIdx.x * THREADS + threadIdx.x) * PPT;  // first pixel
    const int b = q >> 18;            // q / HW_
    const int s = q & (HW_ - 1);      // q % HW_
    const float* base = logits + (size_t)b * CC * HW_ + s;

    const int4 tg4 = *reinterpret_cast<const int4*>(targets + q);
    const int tgt[4]  = {tg4.x, tg4.y, tg4.z, tg4.w};

    // Direct gather of the target logit: log p(level2) = v_t - log(total).
    // Same 128B lines as the channel loads -> sector-merged, no extra DRAM.
    float vt[4];
#pragma unroll
    for (int j = 0; j < 4; ++j)
        vt[j] = __ldg(base + (size_t)tgt[j] * HW_ + j);

    const int tgrp[4] = {tgt[0] / 5, tgt[1] / 5, tgt[2] / 5, tgt[3] / 5};

    float lo[4] = {0.f, 0.f, 0.f, 0.f};   // sum exp over channels 0..9
    float hi[4] = {0.f, 0.f, 0.f, 0.f};   // sum exp over channels 10..19
    float g5[4] = {0.f, 0.f, 0.f, 0.f};   // sum exp over target's 5-group

    // ---- software-pipelined phases: prefetch group g+1 before computing g ----
    float4 w[2][5];
#pragma unroll
    for (int k = 0; k < 5; ++k)            // prologue: group 0 loads
        w[0][k] = *reinterpret_cast<const float4*>(base + (size_t)k * HW_);

#pragma unroll
    for (int g = 0; g < 4; ++g) {
        const int cur = g & 1;
        if (g < 3) {                       // issue next group's loads FIRST
            const int nxt = cur ^ 1;
#pragma unroll
            for (int k = 0; k < 5; ++k)
                w[nxt][k] = *reinterpret_cast<const float4*>(
                                base + (size_t)((g + 1) * 5 + k) * HW_);
        }

        float sg[4] = {0.f, 0.f, 0.f, 0.f};
#pragma unroll
        for (int k = 0; k < 5; ++k) {
            sg[0] += __expf(w[cur][k].x);
            sg[1] += __expf(w[cur][k].y);
            sg[2] += __expf(w[cur][k].z);
            sg[3] += __expf(w[cur][k].w);
        }
#pragma unroll
        for (int j = 0; j < 4; ++j) {
            if (g < 2) lo[j] += sg[j]; else hi[j] += sg[j];   // compile-time split
            g5[j] = (tgrp[j] == g) ? sg[j] : g5[j];           // 1 select per group
        }
    }

    float a0 = 0.f, a1 = 0.f, a2 = 0.f, a3 = 0.f;
#pragma unroll
    for (int j = 0; j < 4; ++j) {
        const float total = lo[j] + hi[j];
        const float g10   = (tgt[j] < 10) ? lo[j] : hi[j];
        a0 += __logf(g10);
        a1 += __logf(g5[j]);
        a2 += vt[j];                       // log(exp(v_t)) = v_t, exact
        a3 += __logf(total);
    }

    __shared__ float sm0[THREADS / 32], sm1[THREADS / 32],
                     sm2[THREADS / 32], sm3[THREADS / 32];
    block_reduce4(a0, a1, a2, a3, sm0, sm1, sm2, sm3);

    __shared__ bool is_last;
    if (threadIdx.x == 0) {
        g_part0[blockIdx.x] = a0;
        g_part1[blockIdx.x] = a1;
        g_part2[blockIdx.x] = a2;
        g_part3[blockIdx.x] = a3;
        __threadfence();
        const unsigned prev = atomicAdd(&g_count, 1u);
        is_last = (prev == GRID - 1);
    }
    __syncthreads();

    if (!is_last) return;

    // ---- last block: reduce all 2048 partials in fixed order, write output ----
    float r0 = 0.f, r1 = 0.f, r2 = 0.f, r3 = 0.f;
#pragma unroll 4
    for (int i = threadIdx.x; i < GRID; i += THREADS) {
        r0 += g_part0[i];
        r1 += g_part1[i];
        r2 += g_part2[i];
        r3 += g_part3[i];
    }
    block_reduce4(r0, r1, r2, r3, sm0, sm1, sm2, sm3);

    if (threadIdx.x == 0) {
        const double n  = (double)NPIX;
        const double lt = (double)r3;                // sum log(total)
        const double l0 = -((double)r0 - lt) / n;    // -mean(log p0)
        const double l1 = -((double)r1 - lt) / n;
        const double l2 = -((double)r2 - lt) / n;
        const double tot = l0 + l1 + l2;

        if (out_size == 3) {                 // levels-only fallback layout
            out[0] = (float)l0; out[1] = (float)l1; out[2] = (float)l2;
        } else {                             // (loss, level_losses) flattened
            if (out_size > 0) out[0] = (float)tot;
            if (out_size > 1) out[1] = (float)l0;
            if (out_size > 2) out[2] = (float)l1;
            if (out_size > 3) out[3] = (float)l2;
            for (int i = 4; i < out_size; ++i) out[i] = 0.f;
        }
        g_count = 0;                         // self-restore for next graph replay
    }
}

extern "C" void kernel_launch(void* const* d_in, const int* in_sizes, int n_in,
                              void* d_out, int out_size) {
    const float* logits  = (const float*)d_in[0];
    const int*   targets = (const int*)d_in[1];
    float*       out     = (float*)d_out;

    tce_kernel<<<GRID, THREADS>>>(logits, targets, out, out_size);
}

// round 8
// speedup vs baseline: 1.1109x; 1.1109x over previous
#include <cuda_runtime.h>

// Fixed problem shape
#define CC      20
#define HW_     (512 * 512)           // 262144 = 2^18
#define BATCH_  8
#define NPIX    (BATCH_ * HW_)        // 2,097,152 pixels
#define THREADS 256
#define PPT     4
#define GRID    (NPIX / (THREADS * PPT))   // 2048 blocks

// Global accumulators (statically zero; finalize self-resets after each read,
// so every graph replay starts from zero without an init kernel).
__device__ double g_acc[4] = {0.0, 0.0, 0.0, 0.0};  // [log g10, log g5, v_t, log total]

__device__ __forceinline__ void block_reduce4(float& a0, float& a1, float& a2, float& a3,
                                              float* sm0, float* sm1, float* sm2, float* sm3)
{
#pragma unroll
    for (int off = 16; off > 0; off >>= 1) {
        a0 += __shfl_down_sync(0xFFFFFFFFu, a0, off);
        a1 += __shfl_down_sync(0xFFFFFFFFu, a1, off);
        a2 += __shfl_down_sync(0xFFFFFFFFu, a2, off);
        a3 += __shfl_down_sync(0xFFFFFFFFu, a3, off);
    }
    const int lane = threadIdx.x & 31;
    const int wid  = threadIdx.x >> 5;
    if (lane == 0) { sm0[wid] = a0; sm1[wid] = a1; sm2[wid] = a2; sm3[wid] = a3; }
    __syncthreads();
    if (wid == 0) {
        const int nw = THREADS / 32;
        a0 = (lane < nw) ? sm0[lane] : 0.f;
        a1 = (lane < nw) ? sm1[lane] : 0.f;
        a2 = (lane < nw) ? sm2[lane] : 0.f;
        a3 = (lane < nw) ? sm3[lane] : 0.f;
#pragma unroll
        for (int off = 4; off > 0; off >>= 1) {
            a0 += __shfl_down_sync(0xFFFFFFFFu, a0, off);
            a1 += __shfl_down_sync(0xFFFFFFFFu, a1, off);
            a2 += __shfl_down_sync(0xFFFFFFFFu, a2, off);
            a3 += __shfl_down_sync(0xFFFFFFFFu, a3, off);
        }
    }
}

__global__ __launch_bounds__(THREADS)
void tce_main_kernel(const float* __restrict__ logits,
                     const int*   __restrict__ targets)
{
    const int q = (blockIdx.x * THREADS + threadIdx.x) * PPT;  // first pixel
    const int b = q >> 18;            // q / HW_
    const int s = q & (HW_ - 1);      // q % HW_
    const float* base = logits + (size_t)b * CC * HW_ + s;

    const int4 tg4 = *reinterpret_cast<const int4*>(targets + q);
    const int tgt[4] = {tg4.x, tg4.y, tg4.z, tg4.w};

    // ---- front-batched loads: 20 independent coalesced LDG.128 ----
    float4 v[CC];
#pragma unroll
    for (int c = 0; c < CC; ++c)
        v[c] = *reinterpret_cast<const float4*>(base + (size_t)c * HW_);

    // Target-logit gather AFTER the stream loads: same 128B lines, L1 hits.
    // log p(level2) = v_t - log(total), exactly.
    float vt[4];
#pragma unroll
    for (int j = 0; j < 4; ++j)
        vt[j] = __ldg(base + (size_t)tgt[j] * HW_ + j);

    float a0 = 0.f, a1 = 0.f, a2 = 0.f, a3 = 0.f;

#pragma unroll
    for (int j = 0; j < 4; ++j) {
        const int t = tgt[j];
        // No max-subtraction: softmax is shift-invariant, logits bounded.
        float s0 = 0.f, s1 = 0.f, s2 = 0.f, s3 = 0.f;
#pragma unroll
        for (int c = 0; c < CC; ++c) {
            const float e = __expf(reinterpret_cast<const float*>(&v[c])[j]);
            if      (c < 5)  s0 += e;
            else if (c < 10) s1 += e;
            else if (c < 15) s2 += e;
            else             s3 += e;
        }
        const float lo = s0 + s1;
        const float hi = s2 + s3;
        const float g10 = (t < 10) ? lo : hi;
        const float g5  = (t < 5) ? s0 : (t < 10) ? s1 : (t < 15) ? s2 : s3;

        a0 += __logf(g10);
        a1 += __logf(g5);
        a2 += vt[j];
        a3 += __logf(lo + hi);
    }

    __shared__ float sm0[THREADS / 32], sm1[THREADS / 32],
                     sm2[THREADS / 32], sm3[THREADS / 32];
    block_reduce4(a0, a1, a2, a3, sm0, sm1, sm2, sm3);

    if (threadIdx.x == 0) {
        atomicAdd(&g_acc[0], (double)a0);
        atomicAdd(&g_acc[1], (double)a1);
        atomicAdd(&g_acc[2], (double)a2);
        atomicAdd(&g_acc[3], (double)a3);
    }
}

__global__ void tce_finalize_kernel(float* __restrict__ out, int out_size) {
    if (threadIdx.x != 0 || blockIdx.x != 0) return;
    const double n  = (double)NPIX;
    const double lt = g_acc[3];                   // sum log(total)
    const double l0 = -(g_acc[0] - lt) / n;       // -mean(log p0)
    const double l1 = -(g_acc[1] - lt) / n;
    const double l2 = -(g_acc[2] - lt) / n;
    const double tot = l0 + l1 + l2;

    if (out_size == 3) {                 // levels-only fallback layout
        out[0] = (float)l0; out[1] = (float)l1; out[2] = (float)l2;
    } else {                             // (loss, level_losses) flattened
        if (out_size > 0) out[0] = (float)tot;
        if (out_size > 1) out[1] = (float)l0;
        if (out_size > 2) out[2] = (float)l1;
        if (out_size > 3) out[3] = (float)l2;
        for (int i = 4; i < out_size; ++i) out[i] = 0.f;
    }
    // Self-reset so the next graph replay starts from zero.
    g_acc[0] = 0.0; g_acc[1] = 0.0; g_acc[2] = 0.0; g_acc[3] = 0.0;
}

extern "C" void kernel_launch(void* const* d_in, const int* in_sizes, int n_in,
                              void* d_out, int out_size) {
    const float* logits  = (const float*)d_in[0];
    const int*   targets = (const int*)d_in[1];
    float*       out     = (float*)d_out;

    tce_main_kernel<<<GRID, THREADS>>>(logits, targets);
    tce_finalize_kernel<<<1, 32>>>(out, out_size);
}

// round 9
// speedup vs baseline: 1.1158x; 1.0044x over previous
#include <cuda_runtime.h>
#include <cstdint>

// Fixed problem shape
#define CC      20
#define HW_     (512 * 512)           // 262144 = 2^18
#define BATCH_  8
#define NPIX    (BATCH_ * HW_)        // 2,097,152 pixels
#define THREADS 256
#define CHUNK   256                   // pixels per chunk (1 per thread)
#define CPB     4                     // chunks per block
#define GRID    (NPIX / (CHUNK * CPB))     // 2048 blocks
#define CH_BYTES    (CHUNK * 4)            // 1024 B per channel per chunk
#define STAGE_BYTES (CC * CH_BYTES)        // 20480 B per stage

// Global accumulators; finalize self-resets, so replays start from zero.
__device__ double g_acc[4] = {0.0, 0.0, 0.0, 0.0};

__device__ __forceinline__ uint32_t smem_u32(const void* p) {
    uint32_t a;
    asm("{ .reg .u64 t; cvta.to.shared.u64 t, %1; cvt.u32.u64 %0, t; }"
        : "=r"(a) : "l"(p));
    return a;
}

#define MBAR_INIT(addr, cnt) \
    asm volatile("mbarrier.init.shared.b64 [%0], %1;" :: "r"(addr), "r"(cnt) : "memory")

#define MBAR_EXPECT(addr, bytes) \
    asm volatile("mbarrier.arrive.expect_tx.shared.b64 _, [%0], %1;" \
                 :: "r"(addr), "r"(bytes) : "memory")

#define BULK_G2S(dst, src, bytes, mbar) \
    asm volatile("cp.async.bulk.shared::cluster.global.mbarrier::complete_tx::bytes " \
                 "[%0], [%1], %2, [%3];" \
                 :: "r"(dst), "l"(src), "r"(bytes), "r"(mbar) : "memory")

__device__ __forceinline__ void mbar_wait(uint32_t mbar, uint32_t parity) {
    asm volatile(
        "{\n\t"
        ".reg .pred P;\n\t"
        "WAIT_%=:\n\t"
        "mbarrier.try_wait.parity.acquire.cta.shared::cta.b64 P, [%0], %1, 0x989680;\n\t"
        "@P bra.uni DONE_%=;\n\t"
        "bra.uni WAIT_%=;\n\t"
        "DONE_%=:\n\t"
        "}" :: "r"(mbar), "r"(parity) : "memory");
}

__device__ __forceinline__ void block_reduce4(float& a0, float& a1, float& a2, float& a3,
                                              float* sm0, float* sm1, float* sm2, float* sm3)
{
#pragma unroll
    for (int off = 16; off > 0; off >>= 1) {
        a0 += __shfl_down_sync(0xFFFFFFFFu, a0, off);
        a1 += __shfl_down_sync(0xFFFFFFFFu, a1, off);
        a2 += __shfl_down_sync(0xFFFFFFFFu, a2, off);
        a3 += __shfl_down_sync(0xFFFFFFFFu, a3, off);
    }
    const int lane = threadIdx.x & 31;
    const int wid  = threadIdx.x >> 5;
    if (lane == 0) { sm0[wid] = a0; sm1[wid] = a1; sm2[wid] = a2; sm3[wid] = a3; }
    __syncthreads();
    if (wid == 0) {
        const int nw = THREADS / 32;
        a0 = (lane < nw) ? sm0[lane] : 0.f;
        a1 = (lane < nw) ? sm1[lane] : 0.f;
        a2 = (lane < nw) ? sm2[lane] : 0.f;
        a3 = (lane < nw) ? sm3[lane] : 0.f;
#pragma unroll
        for (int off = 4; off > 0; off >>= 1) {
            a0 += __shfl_down_sync(0xFFFFFFFFu, a0, off);
            a1 += __shfl_down_sync(0xFFFFFFFFu, a1, off);
            a2 += __shfl_down_sync(0xFFFFFFFFu, a2, off);
            a3 += __shfl_down_sync(0xFFFFFFFFu, a3, off);
        }
    }
}

__global__ __launch_bounds__(THREADS)
void tce_main_kernel(const float* __restrict__ logits,
                     const int*   __restrict__ targets)
{
    // 2 stages x 20 channels x 256 pixels. Channel pitch = 1024B = 0 mod 32
    // banks -> all LDS below are conflict-free.
    __shared__ __align__(128) float tile[2][CC][CHUNK];
    __shared__ __align__(8)  unsigned long long mbar_store[2];

    const int tid  = threadIdx.x;
    const int pix0 = blockIdx.x * (CHUNK * CPB);     // block's first pixel
    const int b    = pix0 >> 18;                     // batch (block never crosses)
    const int s0   = pix0 & (HW_ - 1);               // offset within plane
    const float* plane = logits + (size_t)b * CC * HW_ + s0;

    const uint32_t mb[2] = { smem_u32(&mbar_store[0]), smem_u32(&mbar_store[1]) };

    if (tid == 0) { MBAR_INIT(mb[0], 1); MBAR_INIT(mb[1], 1); }
    __syncthreads();

    // Prologue: fill both stages (chunks 0 and 1).
    if (tid == 0) {
#pragma unroll
        for (int st = 0; st < 2; ++st) {
            MBAR_EXPECT(mb[st], STAGE_BYTES);
#pragma unroll
            for (int c = 0; c < CC; ++c)
                BULK_G2S(smem_u32(&tile[st][c][0]),
                         plane + (size_t)c * HW_ + st * CHUNK,
                         CH_BYTES, mb[st]);
        }
    }

    float a0 = 0.f, a1 = 0.f, a2 = 0.f, a3 = 0.f;

#pragma unroll
    for (int i = 0; i < CPB; ++i) {
        const int st = i & 1;
        const int ph = (i >> 1) & 1;
        mbar_wait(mb[st], ph);

        const int q = pix0 + i * CHUNK + tid;
        const int t = __ldg(targets + q);

        float s0_ = 0.f, s1_ = 0.f, s2_ = 0.f, s3_ = 0.f;
#pragma unroll
        for (int c = 0; c < CC; ++c) {
            const float e = __expf(tile[st][c][tid]);
            if      (c < 5)  s0_ += e;
            else if (c < 10) s1_ += e;
            else if (c < 15) s2_ += e;
            else             s3_ += e;
        }
        const float vt = tile[st][t][tid];          // raw target logit from SMEM
        const float lo = s0_ + s1_;
        const float hi = s2_ + s3_;
        const float g10 = (t < 10) ? lo : hi;
        const float g5  = (t < 5) ? s0_ : (t < 10) ? s1_ : (t < 15) ? s2_ : s3_;

        a0 += __logf(g10);
        a1 += __logf(g5);
        a2 += vt;                                   // log p2 = v_t - log(total)
        a3 += __logf(lo + hi);

        __syncthreads();                            // stage fully consumed
        if (i + 2 < CPB && tid == 0) {              // refill with chunk i+2
            MBAR_EXPECT(mb[st], STAGE_BYTES);
#pragma unroll
            for (int c = 0; c < CC; ++c)
                BULK_G2S(smem_u32(&tile[st][c][0]),
                         plane + (size_t)c * HW_ + (i + 2) * CHUNK,
                         CH_BYTES, mb[st]);
        }
    }

    __shared__ float sm0[THREADS / 32], sm1[THREADS / 32],
                     sm2[THREADS / 32], sm3[THREADS / 32];
    block_reduce4(a0, a1, a2, a3, sm0, sm1, sm2, sm3);

    if (threadIdx.x == 0) {
        atomicAdd(&g_acc[0], (double)a0);
        atomicAdd(&g_acc[1], (double)a1);
        atomicAdd(&g_acc[2], (double)a2);
        atomicAdd(&g_acc[3], (double)a3);
    }
}

__global__ void tce_finalize_kernel(float* __restrict__ out, int out_size) {
    if (threadIdx.x != 0 || blockIdx.x != 0) return;
    const double n  = (double)NPIX;
    const double lt = g_acc[3];                   // sum log(total)
    const double l0 = -(g_acc[0] - lt) / n;       // -mean(log p0)
    const double l1 = -(g_acc[1] - lt) / n;
    const double l2 = -(g_acc[2] - lt) / n;
    const double tot = l0 + l1 + l2;

    if (out_size == 3) {                 // levels-only fallback layout
        out[0] = (float)l0; out[1] = (float)l1; out[2] = (float)l2;
    } else {                             // (loss, level_losses) flattened
        if (out_size > 0) out[0] = (float)tot;
        if (out_size > 1) out[1] = (float)l0;
        if (out_size > 2) out[2] = (float)l1;
        if (out_size > 3) out[3] = (float)l2;
        for (int i = 4; i < out_size; ++i) out[i] = 0.f;
    }
    g_acc[0] = 0.0; g_acc[1] = 0.0; g_acc[2] = 0.0; g_acc[3] = 0.0;
}

extern "C" void kernel_launch(void* const* d_in, const int* in_sizes, int n_in,
                              void* d_out, int out_size) {
    const float* logits  = (const float*)d_in[0];
    const int*   targets = (const int*)d_in[1];
    float*       out     = (float*)d_out;

    tce_main_kernel<<<GRID, THREADS>>>(logits, targets);
    tce_finalize_kernel<<<1, 32>>>(out, out_size);
}